// round 1
// baseline (speedup 1.0000x reference)
#include <cuda_runtime.h>
#include <math.h>

// ---------------- problem constants ----------------
#define Bb   8
#define NT   1024
#define Dm   768
#define Hh   8
#define Ss   3072
#define HDk  384
#define ROWS (Bb * NT)            // 8192
#define EPSF 1e-6f
#define LNEPS 1e-5f
#define PERSISTF 0.95f

// ---------------- scratch (static device memory; no runtime alloc) ----------------
__device__ float g_xn[(size_t)ROWS * Dm];                    // normalized x
__device__ float g_res[ROWS];                                // residue gate per token
__device__ float g_xmean[Bb * Dm];                           // token-sum of xn (divide by NT later)
__device__ float g_read[Bb * Hh];
__device__ float g_write[Bb * Hh];
__device__ float g_qf[(size_t)Bb * Hh * NT * HDk];           // feature-mapped q, head layout
__device__ float g_kf[(size_t)Bb * Hh * NT * HDk];           // feature-mapped k (un-normalized)
__device__ float g_v [(size_t)Bb * Hh * NT * HDk];
__device__ float g_ksum[Bb * Hh * HDk];                      // sum_n k
__device__ float g_state[(size_t)Bb * Hh * HDk * HDk];       // normalized k^T v
__device__ float g_mem[Hh * HDk * HDk];                      // updated memory
__device__ float g_y[(size_t)ROWS * Ss];                     // attention read output

// ---------------- helpers ----------------
__device__ __forceinline__ float block_reduce_256(float v, float* sh) {
    __syncthreads();
    int lane = threadIdx.x & 31, w = threadIdx.x >> 5;
#pragma unroll
    for (int o = 16; o; o >>= 1) v += __shfl_down_sync(0xffffffffu, v, o);
    if (lane == 0) sh[w] = v;
    __syncthreads();
    if (threadIdx.x < 32) {
        v = (threadIdx.x < 8) ? sh[threadIdx.x] : 0.f;
#pragma unroll
        for (int o = 4; o; o >>= 1) v += __shfl_down_sync(0xffffffffu, v, o);
        if (threadIdx.x == 0) sh[0] = v;
    }
    __syncthreads();
    return sh[0];
}

__device__ __forceinline__ float sigmoidf_(float z) {
    return 1.f / (1.f + expf(-z));
}

// ---------------- 1) LayerNorm + residue gate ----------------
__global__ void ln_kernel(const float* __restrict__ x,
                          const float* __restrict__ lng,
                          const float* __restrict__ lnb,
                          const float* __restrict__ wres,
                          const float* __restrict__ bres) {
    __shared__ float sh[32];
    int row = blockIdx.x;
    const float* xr = x + (size_t)row * Dm;
    float v[3];
#pragma unroll
    for (int j = 0; j < 3; j++) v[j] = xr[threadIdx.x + 256 * j];
    float s  = v[0] + v[1] + v[2];
    float sq = v[0]*v[0] + v[1]*v[1] + v[2]*v[2];
    float tot  = block_reduce_256(s, sh);
    float totq = block_reduce_256(sq, sh);
    float mu   = tot * (1.f / Dm);
    float var  = totq * (1.f / Dm) - mu * mu;
    float rstd = rsqrtf(var + LNEPS);
    float dot = 0.f;
#pragma unroll
    for (int j = 0; j < 3; j++) {
        int i = threadIdx.x + 256 * j;
        float xn = (v[j] - mu) * rstd * lng[i] + lnb[i];
        g_xn[(size_t)row * Dm + i] = xn;
        dot += xn * wres[i];
    }
    float dt = block_reduce_256(dot, sh);
    if (threadIdx.x == 0) g_res[row] = sigmoidf_(dt + bres[0]);
}

// ---------------- 2) zero accumulators ----------------
__global__ void zero_kernel() {
    int i = blockIdx.x * 256 + threadIdx.x;
    if (i < Bb * Dm)        g_xmean[i] = 0.f;
    if (i < Bb * Hh * HDk)  g_ksum[i]  = 0.f;
}

// ---------------- 3) column mean of xn over tokens (partial + atomic) ----------------
__global__ void colmean_kernel() {
    int idx = blockIdx.x * 256 + threadIdx.x;         // < Bb*Dm*16
    int c   = idx / (Bb * Dm);
    int rem = idx % (Bb * Dm);
    int b = rem / Dm, d = rem % Dm;
    const float* p = g_xn + ((size_t)b * NT + (size_t)c * 64) * Dm + d;
    float s = 0.f;
#pragma unroll 4
    for (int n = 0; n < 64; n++) s += p[(size_t)n * Dm];
    atomicAdd(&g_xmean[rem], s);
}

// ---------------- 4) read/write gates ----------------
__global__ void gates_kernel(const float* __restrict__ wrg, const float* __restrict__ brg,
                             const float* __restrict__ wwg, const float* __restrict__ bwg) {
    int t = threadIdx.x;
    if (t >= Bb * Hh) return;
    int b = t / Hh, h = t % Hh;
    float ar = 0.f, aw = 0.f;
    for (int d = 0; d < Dm; d++) {
        float xm = g_xmean[b * Dm + d] * (1.f / NT);
        ar += xm * wrg[d * Hh + h];
        aw += xm * wwg[d * Hh + h];
    }
    g_read[t]  = sigmoidf_(ar + brg[h]);
    g_write[t] = sigmoidf_(aw + bwg[h]);
}

// ---------------- big GEMM: 128x128 tile, 8x8 per thread, K-step 8 ----------------
// MODE 0: g_xn[8192,768] @ w_in[768,9216] + b_in -> feature map -> g_qf/g_kf/g_v (head layout)
// MODE 1: g_y[8192,3072] @ w_out[3072,768] + b_out -> gated residual -> out
template <int MODE>
__global__ void gemm_big(const float* __restrict__ Bw,
                         const float* __restrict__ bias,
                         const float* __restrict__ xin,
                         float* __restrict__ out) {
    constexpr int K  = (MODE == 0) ? Dm : Ss;
    constexpr int NC = (MODE == 0) ? 3 * Ss : Dm;
    const float* A = (MODE == 0) ? g_xn : g_y;

    __shared__ float As[8][128];
    __shared__ float Bs[8][128];

    const int t  = threadIdx.x;
    const int tx = t & 15, ty = t >> 4;
    const int trow = blockIdx.y * 128, tcol = blockIdx.x * 128;

    const int arow = t >> 1, ak = (t & 1) * 4;
    const int bk   = t >> 5, bcol = (t & 31) * 4;

    const float* Ap = A  + (size_t)(trow + arow) * K + ak;
    const float* Bp = Bw + (size_t)bk * NC + tcol + bcol;

    float acc[8][8] = {};

    for (int k0 = 0; k0 < K; k0 += 8) {
        float4 a4 = *(const float4*)(Ap + k0);
        float4 b4 = *(const float4*)(Bp + (size_t)k0 * NC);
        As[ak + 0][arow] = a4.x; As[ak + 1][arow] = a4.y;
        As[ak + 2][arow] = a4.z; As[ak + 3][arow] = a4.w;
        *(float4*)&Bs[bk][bcol] = b4;
        __syncthreads();
#pragma unroll
        for (int kk = 0; kk < 8; kk++) {
            float4 a0 = *(const float4*)&As[kk][ty * 8];
            float4 a1 = *(const float4*)&As[kk][ty * 8 + 4];
            float4 b0 = *(const float4*)&Bs[kk][tx * 8];
            float4 b1 = *(const float4*)&Bs[kk][tx * 8 + 4];
            float ar[8] = {a0.x, a0.y, a0.z, a0.w, a1.x, a1.y, a1.z, a1.w};
            float br[8] = {b0.x, b0.y, b0.z, b0.w, b1.x, b1.y, b1.z, b1.w};
#pragma unroll
            for (int i = 0; i < 8; i++)
#pragma unroll
                for (int j = 0; j < 8; j++)
                    acc[i][j] = fmaf(ar[i], br[j], acc[i][j]);
        }
        __syncthreads();
    }

#pragma unroll
    for (int i = 0; i < 8; i++) {
        int row = trow + ty * 8 + i;
#pragma unroll
        for (int j = 0; j < 8; j++) {
            int col = tcol + tx * 8 + j;
            float val = acc[i][j] + bias[col];
            if (MODE == 0) {
                int b = row >> 10, n = row & 1023;
                int region = col / Ss;
                int sIn = col - region * Ss;
                int h = sIn / HDk, d = sIn - h * HDk;
                size_t idx = (((size_t)(b * Hh + h)) * NT + n) * HDk + d;
                if (region == 2) {
                    g_v[idx] = val;
                } else {
                    float p = fmaxf(val, 0.f) + EPSF;
                    float f = p * sqrtf(p);       // (relu+eps)^1.5
                    if (region == 0) g_qf[idx] = f; else g_kf[idx] = f;
                }
            } else {
                float r = g_res[row];
                size_t o = (size_t)row * Dm + col;
                out[o] = r * val + (1.f - r) * xin[o];
            }
        }
    }
}

// ---------------- 6) ksum over tokens (partial + atomic) ----------------
__global__ void ksum_kernel() {
    int idx = blockIdx.x * 256 + threadIdx.x;           // < Bb*Hh*HDk*8
    int c   = idx / (Bb * Hh * HDk);
    int rem = idx % (Bb * Hh * HDk);
    int bh = rem / HDk, d = rem % HDk;
    const float* p = g_kf + ((size_t)bh * NT + (size_t)c * 128) * HDk + d;
    float s = 0.f;
#pragma unroll 4
    for (int n = 0; n < 128; n++) s += p[(size_t)n * HDk];
    atomicAdd(&g_ksum[rem], s);
}

// ---------------- 7) state = (k^T v) / (ksum + eps), per (b,h) ----------------
__global__ void state_kernel() {
    int bh = blockIdx.z;
    int d0 = blockIdx.y * 64, e0 = blockIdx.x * 64;
    const float* kp = g_kf + (size_t)bh * NT * HDk;
    const float* vp = g_v  + (size_t)bh * NT * HDk;
    __shared__ float ks[16][64], vs[16][64];
    int t = threadIdx.x, tx = t & 15, ty = t >> 4;
    int ln = t >> 4, lc = (t & 15) * 4;
    float acc[4][4] = {};
    for (int n0 = 0; n0 < NT; n0 += 16) {
        *(float4*)&ks[ln][lc] = *(const float4*)(kp + (size_t)(n0 + ln) * HDk + d0 + lc);
        *(float4*)&vs[ln][lc] = *(const float4*)(vp + (size_t)(n0 + ln) * HDk + e0 + lc);
        __syncthreads();
#pragma unroll
        for (int nn = 0; nn < 16; nn++) {
            float4 av = *(const float4*)&ks[nn][ty * 4];
            float4 bv = *(const float4*)&vs[nn][tx * 4];
            float a[4] = {av.x, av.y, av.z, av.w};
            float b[4] = {bv.x, bv.y, bv.z, bv.w};
#pragma unroll
            for (int i = 0; i < 4; i++)
#pragma unroll
                for (int j = 0; j < 4; j++)
                    acc[i][j] = fmaf(a[i], b[j], acc[i][j]);
        }
        __syncthreads();
    }
#pragma unroll
    for (int i = 0; i < 4; i++) {
        float inv = 1.f / (g_ksum[bh * HDk + d0 + ty * 4 + i] + EPSF);
#pragma unroll
        for (int j = 0; j < 4; j++)
            g_state[((size_t)bh * HDk + d0 + ty * 4 + i) * HDk + e0 + tx * 4 + j] = acc[i][j] * inv;
    }
}

// ---------------- 8) EMA memory update ----------------
__global__ void memup_kernel(const float* __restrict__ mem) {
    int idx = blockIdx.x * 256 + threadIdx.x;           // < Hh*HDk*HDk
    int h  = idx / (HDk * HDk);
    int de = idx - h * HDk * HDk;
    float ss = 0.f, sw = 0.f;
#pragma unroll
    for (int b = 0; b < Bb; b++) {
        ss += g_state[((size_t)(b * Hh + h)) * HDk * HDk + de];
        sw += g_write[b * Hh + h];
    }
    g_mem[idx] = PERSISTF * mem[idx]
               + (1.f - PERSISTF) * (sw * (1.f / Bb)) * (ss * (1.f / Bb));
}

// ---------------- 9) y = read * (q @ mem_new), per (b,h) ----------------
__global__ void y_kernel() {
    int bh = blockIdx.z;
    int h = bh & 7, b = bh >> 3;
    int n0 = blockIdx.y * 64, e0 = blockIdx.x * 64;
    const float* qp = g_qf  + (size_t)bh * NT * HDk;
    const float* mp = g_mem + (size_t)h * HDk * HDk;
    float rg = g_read[bh];
    __shared__ float qs[16][64], ms[16][64];
    int t = threadIdx.x, tx = t & 15, ty = t >> 4;
    int qn = t >> 2, qk = (t & 3) * 4;
    int md = t >> 4, me = (t & 15) * 4;
    float acc[4][4] = {};
    for (int k0 = 0; k0 < HDk; k0 += 16) {
        float4 q4 = *(const float4*)(qp + (size_t)(n0 + qn) * HDk + k0 + qk);
        qs[qk + 0][qn] = q4.x; qs[qk + 1][qn] = q4.y;
        qs[qk + 2][qn] = q4.z; qs[qk + 3][qn] = q4.w;
        *(float4*)&ms[md][me] = *(const float4*)(mp + (size_t)(k0 + md) * HDk + e0 + me);
        __syncthreads();
#pragma unroll
        for (int kk = 0; kk < 16; kk++) {
            float4 av = *(const float4*)&qs[kk][ty * 4];
            float4 bv = *(const float4*)&ms[kk][tx * 4];
            float a[4] = {av.x, av.y, av.z, av.w};
            float bq[4] = {bv.x, bv.y, bv.z, bv.w};
#pragma unroll
            for (int i = 0; i < 4; i++)
#pragma unroll
                for (int j = 0; j < 4; j++)
                    acc[i][j] = fmaf(a[i], bq[j], acc[i][j]);
        }
        __syncthreads();
    }
#pragma unroll
    for (int i = 0; i < 4; i++) {
        size_t rbase = ((size_t)(b * NT + n0 + ty * 4 + i)) * Ss + h * HDk + e0 + tx * 4;
#pragma unroll
        for (int j = 0; j < 4; j++)
            g_y[rbase + j] = rg * acc[i][j];
    }
}

// ---------------- launch ----------------
extern "C" void kernel_launch(void* const* d_in, const int* in_sizes, int n_in,
                              void* d_out, int out_size) {
    const float* x     = (const float*)d_in[0];
    const float* mem   = (const float*)d_in[1];
    const float* lng   = (const float*)d_in[2];
    const float* lnb   = (const float*)d_in[3];
    const float* w_in  = (const float*)d_in[4];
    const float* b_in  = (const float*)d_in[5];
    const float* w_out = (const float*)d_in[6];
    const float* b_out = (const float*)d_in[7];
    const float* w_rg  = (const float*)d_in[8];
    const float* b_rg  = (const float*)d_in[9];
    const float* w_wg  = (const float*)d_in[10];
    const float* b_wg  = (const float*)d_in[11];
    const float* w_res = (const float*)d_in[12];
    const float* b_res = (const float*)d_in[13];
    float* out = (float*)d_out;

    ln_kernel<<<ROWS, 256>>>(x, lng, lnb, w_res, b_res);
    zero_kernel<<<(Bb * Hh * HDk + 255) / 256, 256>>>();
    colmean_kernel<<<Bb * Dm * 16 / 256, 256>>>();
    gates_kernel<<<1, 64>>>(w_rg, b_rg, w_wg, b_wg);

    gemm_big<0><<<dim3(3 * Ss / 128, ROWS / 128), 256>>>(w_in, b_in, nullptr, nullptr);

    ksum_kernel<<<Bb * Hh * HDk * 8 / 256, 256>>>();
    state_kernel<<<dim3(HDk / 64, HDk / 64, Bb * Hh), 256>>>();
    memup_kernel<<<Hh * HDk * HDk / 256, 256>>>(mem);
    y_kernel<<<dim3(HDk / 64, NT / 64, Bb * Hh), 256>>>();

    gemm_big<1><<<dim3(Dm / 128, ROWS / 128), 256>>>(w_out, b_out, x, out);
}

// round 2
// speedup vs baseline: 2.4634x; 2.4634x over previous
#include <cuda_runtime.h>
#include <math.h>
#include <stdint.h>

// ---------------- problem constants ----------------
#define Bb   8
#define NT   1024
#define Dm   768
#define Hh   8
#define Ss   3072
#define HDk  384
#define ROWS (Bb * NT)            // 8192
#define EPSF 1e-6f
#define LNEPS 1e-5f
#define PERSISTF 0.95f

// ---------------- scratch (static device memory; no runtime alloc) ----------------
__device__ float g_xn[(size_t)ROWS * Dm];                    // normalized x
__device__ float g_res[ROWS];                                // residue gate per token
__device__ float g_xmean[Bb * Dm];                           // token-sum of xn
__device__ float g_read[Bb * Hh];
__device__ float g_write[Bb * Hh];
__device__ float g_qf[(size_t)Bb * Hh * NT * HDk];           // feature-mapped q, head layout
__device__ float g_kf[(size_t)Bb * Hh * NT * HDk];           // feature-mapped k (un-normalized)
__device__ float g_v [(size_t)Bb * Hh * NT * HDk];
__device__ float g_ksum[Bb * Hh * HDk];                      // sum_n k
__device__ float g_state[(size_t)Bb * Hh * HDk * HDk];       // normalized k^T v
__device__ float g_mem[Hh * HDk * HDk];                      // updated memory
__device__ float g_y[(size_t)ROWS * Ss];                     // attention read output

// ---------------- helpers ----------------
__device__ __forceinline__ float block_reduce_256(float v, float* sh) {
    __syncthreads();
    int lane = threadIdx.x & 31, w = threadIdx.x >> 5;
#pragma unroll
    for (int o = 16; o; o >>= 1) v += __shfl_down_sync(0xffffffffu, v, o);
    if (lane == 0) sh[w] = v;
    __syncthreads();
    if (threadIdx.x < 32) {
        v = (threadIdx.x < 8) ? sh[threadIdx.x] : 0.f;
#pragma unroll
        for (int o = 4; o; o >>= 1) v += __shfl_down_sync(0xffffffffu, v, o);
        if (threadIdx.x == 0) sh[0] = v;
    }
    __syncthreads();
    return sh[0];
}

__device__ __forceinline__ float sigmoidf_(float z) {
    return 1.f / (1.f + expf(-z));
}

__device__ __forceinline__ uint32_t f2t(float f) {
    uint32_t u;
    asm("cvt.rna.tf32.f32 %0, %1;" : "=r"(u) : "f"(f));
    return u;
}
__device__ __forceinline__ uint4 f4tot(float4 v) {
    return make_uint4(f2t(v.x), f2t(v.y), f2t(v.z), f2t(v.w));
}

__device__ __forceinline__ void mma_tf32(float4& d, const uint32_t a[4],
                                         const uint32_t b[2], const float4& c) {
    asm volatile(
        "mma.sync.aligned.m16n8k8.row.col.f32.tf32.tf32.f32 "
        "{%0,%1,%2,%3}, {%4,%5,%6,%7}, {%8,%9}, {%10,%11,%12,%13};\n"
        : "=f"(d.x), "=f"(d.y), "=f"(d.z), "=f"(d.w)
        : "r"(a[0]), "r"(a[1]), "r"(a[2]), "r"(a[3]),
          "r"(b[0]), "r"(b[1]),
          "f"(c.x), "f"(c.y), "f"(c.z), "f"(c.w));
}

// ---------------- 1) LayerNorm + residue gate ----------------
__global__ void ln_kernel(const float* __restrict__ x,
                          const float* __restrict__ lng,
                          const float* __restrict__ lnb,
                          const float* __restrict__ wres,
                          const float* __restrict__ bres) {
    __shared__ float sh[32];
    int row = blockIdx.x;
    const float* xr = x + (size_t)row * Dm;
    float v[3];
#pragma unroll
    for (int j = 0; j < 3; j++) v[j] = xr[threadIdx.x + 256 * j];
    float s  = v[0] + v[1] + v[2];
    float sq = v[0]*v[0] + v[1]*v[1] + v[2]*v[2];
    float tot  = block_reduce_256(s, sh);
    float totq = block_reduce_256(sq, sh);
    float mu   = tot * (1.f / Dm);
    float var  = totq * (1.f / Dm) - mu * mu;
    float rstd = rsqrtf(var + LNEPS);
    float dot = 0.f;
#pragma unroll
    for (int j = 0; j < 3; j++) {
        int i = threadIdx.x + 256 * j;
        float xn = (v[j] - mu) * rstd * lng[i] + lnb[i];
        g_xn[(size_t)row * Dm + i] = xn;
        dot += xn * wres[i];
    }
    float dt = block_reduce_256(dot, sh);
    if (threadIdx.x == 0) g_res[row] = sigmoidf_(dt + bres[0]);
}

// ---------------- 2) zero accumulators ----------------
__global__ void zero_kernel() {
    int i = blockIdx.x * 256 + threadIdx.x;
    if (i < Bb * Dm)        g_xmean[i] = 0.f;
    if (i < Bb * Hh * HDk)  g_ksum[i]  = 0.f;
}

// ---------------- 3) column mean of xn over tokens (partial + atomic) ----------------
__global__ void colmean_kernel() {
    int idx = blockIdx.x * 256 + threadIdx.x;         // < Bb*Dm*16
    int c   = idx / (Bb * Dm);
    int rem = idx % (Bb * Dm);
    int b = rem / Dm, d = rem % Dm;
    const float* p = g_xn + ((size_t)b * NT + (size_t)c * 64) * Dm + d;
    float s = 0.f;
#pragma unroll 4
    for (int n = 0; n < 64; n++) s += p[(size_t)n * Dm];
    atomicAdd(&g_xmean[rem], s);
}

// ---------------- 4) read/write gates (parallelized) ----------------
__global__ void gates_kernel(const float* __restrict__ wrg, const float* __restrict__ brg,
                             const float* __restrict__ wwg, const float* __restrict__ bwg) {
    int b = blockIdx.x, t = threadIdx.x;   // 8 blocks x 256 threads
    float ar[Hh], aw[Hh];
#pragma unroll
    for (int h = 0; h < Hh; h++) { ar[h] = 0.f; aw[h] = 0.f; }
    for (int d = t; d < Dm; d += 256) {
        float xm = g_xmean[b * Dm + d] * (1.f / NT);
        const float* wr = &wrg[d * Hh];
        const float* ww = &wwg[d * Hh];
#pragma unroll
        for (int h = 0; h < Hh; h++) {
            ar[h] = fmaf(xm, wr[h], ar[h]);
            aw[h] = fmaf(xm, ww[h], aw[h]);
        }
    }
    __shared__ float sr[Hh], sw[Hh];
    if (t < Hh) { sr[t] = 0.f; sw[t] = 0.f; }
    __syncthreads();
#pragma unroll
    for (int h = 0; h < Hh; h++) {
        float v = ar[h], w = aw[h];
#pragma unroll
        for (int o = 16; o; o >>= 1) {
            v += __shfl_down_sync(0xffffffffu, v, o);
            w += __shfl_down_sync(0xffffffffu, w, o);
        }
        if ((t & 31) == 0) { atomicAdd(&sr[h], v); atomicAdd(&sw[h], w); }
    }
    __syncthreads();
    if (t < Hh) {
        g_read[b * Hh + t]  = sigmoidf_(sr[t] + brg[t]);
        g_write[b * Hh + t] = sigmoidf_(sw[t] + bwg[t]);
    }
}

// ======================= TF32 tensor-core GEMM =======================
// 128x128x16 block tile, 4 warps, each warp 64x64, mma.m16n8k8 tf32.
// MODE 0: g_xn[8192,768] @ w_in[768,9216] (+b_in) -> hub feature map -> g_qf/g_kf/g_v
// MODE 1: g_y [8192,3072] @ w_out[3072,768] (+b_out) -> gated residual -> out
// MODE 2: per bh: kf^T[384,1024] @ v[1024,384] -> /(ksum+eps) -> g_state
// MODE 3: per bh: qf[1024,384] @ mem_new[384,384] -> *read -> g_y
template <int MODE>
__global__ __launch_bounds__(128) void tf32_gemm(const float* __restrict__ Bsrc,
                                                 const float* __restrict__ bias,
                                                 const float* __restrict__ xin,
                                                 float* __restrict__ out) {
    constexpr int Kdim = (MODE == 0) ? Dm : (MODE == 1) ? Ss : (MODE == 2) ? NT : HDk;
    constexpr int ldb  = (MODE == 0) ? 3 * Ss : (MODE == 1) ? Dm : HDk;
    constexpr int NSTEP = Kdim / 16;

    const int bh = blockIdx.z;
    const float* A;
    const float* Bg;
    if (MODE == 0)      { A = g_xn;                         Bg = Bsrc; }
    else if (MODE == 1) { A = g_y;                          Bg = Bsrc; }
    else if (MODE == 2) { A = g_kf + (size_t)bh * NT * HDk; Bg = g_v + (size_t)bh * NT * HDk; }
    else                { A = g_qf + (size_t)bh * NT * HDk; Bg = g_mem + (size_t)(bh & 7) * HDk * HDk; }

    __shared__ uint32_t As[16][136];
    __shared__ uint32_t Bs[16][136];

    const int t    = threadIdx.x;
    const int warp = t >> 5;
    const int lane = t & 31;
    const int lr   = lane >> 2;      // groupID
    const int lq   = lane & 3;       // tid-in-group
    const int wm   = (warp >> 1) * 64;
    const int wn   = (warp & 1) * 64;
    const int trow = blockIdx.y * 128;
    const int tcol = blockIdx.x * 128;

    // global-load register buffers
    float4 aR[4], bR[4];
    const int bkk = t >> 5;          // 0..3
    const int bc4 = (t & 31) * 4;    // 0..124

    auto load_tiles = [&](int k0) {
        if (MODE == 2) {
#pragma unroll
            for (int i = 0; i < 4; i++)
                aR[i] = *(const float4*)(A + (size_t)(k0 + bkk + i * 4) * HDk + trow + bc4);
        } else {
            const float* ap = A + (size_t)(trow + t) * Kdim + k0;
#pragma unroll
            for (int i = 0; i < 4; i++) aR[i] = *(const float4*)(ap + i * 4);
        }
#pragma unroll
        for (int i = 0; i < 4; i++)
            bR[i] = *(const float4*)(Bg + (size_t)(k0 + bkk + i * 4) * ldb + tcol + bc4);
    };
    auto store_tiles = [&]() {
        if (MODE == 2) {
#pragma unroll
            for (int i = 0; i < 4; i++)
                *(uint4*)&As[bkk + i * 4][bc4] = f4tot(aR[i]);
        } else {
#pragma unroll
            for (int i = 0; i < 4; i++) {
                As[i * 4 + 0][t] = f2t(aR[i].x);
                As[i * 4 + 1][t] = f2t(aR[i].y);
                As[i * 4 + 2][t] = f2t(aR[i].z);
                As[i * 4 + 3][t] = f2t(aR[i].w);
            }
        }
#pragma unroll
        for (int i = 0; i < 4; i++)
            *(uint4*)&Bs[bkk + i * 4][bc4] = f4tot(bR[i]);
    };

    float4 acc[4][8];
#pragma unroll
    for (int i = 0; i < 4; i++)
#pragma unroll
        for (int j = 0; j < 8; j++) acc[i][j] = make_float4(0.f, 0.f, 0.f, 0.f);

    load_tiles(0);
    for (int s = 0; s < NSTEP; s++) {
        store_tiles();
        __syncthreads();
        if (s + 1 < NSTEP) load_tiles((s + 1) * 16);
#pragma unroll
        for (int kb = 0; kb < 2; kb++) {
            const int ko = kb * 8;
            uint32_t afr[4][4], bfr[8][2];
#pragma unroll
            for (int mt = 0; mt < 4; mt++) {
                int mb = wm + mt * 16 + lr;
                afr[mt][0] = As[ko + lq][mb];
                afr[mt][1] = As[ko + lq][mb + 8];
                afr[mt][2] = As[ko + lq + 4][mb];
                afr[mt][3] = As[ko + lq + 4][mb + 8];
            }
#pragma unroll
            for (int nt = 0; nt < 8; nt++) {
                int nb = wn + nt * 8 + lr;
                bfr[nt][0] = Bs[ko + lq][nb];
                bfr[nt][1] = Bs[ko + lq + 4][nb];
            }
#pragma unroll
            for (int mt = 0; mt < 4; mt++)
#pragma unroll
                for (int nt = 0; nt < 8; nt++)
                    mma_tf32(acc[mt][nt], afr[mt], bfr[nt], acc[mt][nt]);
        }
        __syncthreads();
    }

    // -------- epilogue --------
    auto epi = [&](int row, int col, float val) {
        if (MODE == 0) {
            float v = val + bias[col];
            int b = row >> 10, n = row & 1023;
            int region = col / Ss;
            int sIn = col - region * Ss;
            int h = sIn / HDk, d = sIn - h * HDk;
            size_t idx = (((size_t)(b * Hh + h)) * NT + n) * HDk + d;
            if (region == 2) {
                g_v[idx] = v;
            } else {
                float p = fmaxf(v, 0.f) + EPSF;
                float f = p * sqrtf(p);
                if (region == 0) g_qf[idx] = f; else g_kf[idx] = f;
            }
        } else if (MODE == 1) {
            float v = val + bias[col];
            float r = g_res[row];
            size_t o = (size_t)row * Dm + col;
            out[o] = r * v + (1.f - r) * xin[o];
        } else if (MODE == 2) {
            float inv = 1.f / (g_ksum[bh * HDk + row] + EPSF);
            g_state[((size_t)bh * HDk + row) * HDk + col] = val * inv;
        } else {
            float rg = g_read[bh];
            int b = bh >> 3, h = bh & 7;
            g_y[((size_t)(b * NT + row)) * Ss + h * HDk + col] = rg * val;
        }
    };

#pragma unroll
    for (int mt = 0; mt < 4; mt++) {
#pragma unroll
        for (int nt = 0; nt < 8; nt++) {
            float4 c = acc[mt][nt];
            int r0 = trow + wm + mt * 16 + lr;
            int c0 = tcol + wn + nt * 8 + 2 * lq;
            epi(r0,     c0,     c.x);
            epi(r0,     c0 + 1, c.y);
            epi(r0 + 8, c0,     c.z);
            epi(r0 + 8, c0 + 1, c.w);
        }
    }
}

// ---------------- ksum over tokens (partial + atomic) ----------------
__global__ void ksum_kernel() {
    int idx = blockIdx.x * 256 + threadIdx.x;           // < Bb*Hh*HDk*8
    int c   = idx / (Bb * Hh * HDk);
    int rem = idx % (Bb * Hh * HDk);
    int bh = rem / HDk, d = rem % HDk;
    const float* p = g_kf + ((size_t)bh * NT + (size_t)c * 128) * HDk + d;
    float s = 0.f;
#pragma unroll 4
    for (int n = 0; n < 128; n++) s += p[(size_t)n * HDk];
    atomicAdd(&g_ksum[rem], s);
}

// ---------------- EMA memory update ----------------
__global__ void memup_kernel(const float* __restrict__ mem) {
    int idx = blockIdx.x * 256 + threadIdx.x;           // < Hh*HDk*HDk
    int h  = idx / (HDk * HDk);
    int de = idx - h * HDk * HDk;
    float ss = 0.f, sw = 0.f;
#pragma unroll
    for (int b = 0; b < Bb; b++) {
        ss += g_state[((size_t)(b * Hh + h)) * HDk * HDk + de];
        sw += g_write[b * Hh + h];
    }
    g_mem[idx] = PERSISTF * mem[idx]
               + (1.f - PERSISTF) * (sw * (1.f / Bb)) * (ss * (1.f / Bb));
}

// ---------------- launch ----------------
extern "C" void kernel_launch(void* const* d_in, const int* in_sizes, int n_in,
                              void* d_out, int out_size) {
    const float* x     = (const float*)d_in[0];
    const float* mem   = (const float*)d_in[1];
    const float* lng   = (const float*)d_in[2];
    const float* lnb   = (const float*)d_in[3];
    const float* w_in  = (const float*)d_in[4];
    const float* b_in  = (const float*)d_in[5];
    const float* w_out = (const float*)d_in[6];
    const float* b_out = (const float*)d_in[7];
    const float* w_rg  = (const float*)d_in[8];
    const float* b_rg  = (const float*)d_in[9];
    const float* w_wg  = (const float*)d_in[10];
    const float* b_wg  = (const float*)d_in[11];
    const float* w_res = (const float*)d_in[12];
    const float* b_res = (const float*)d_in[13];
    float* out = (float*)d_out;

    ln_kernel<<<ROWS, 256>>>(x, lng, lnb, w_res, b_res);
    zero_kernel<<<(Bb * Hh * HDk + 255) / 256, 256>>>();
    colmean_kernel<<<Bb * Dm * 16 / 256, 256>>>();
    gates_kernel<<<Bb, 256>>>(w_rg, b_rg, w_wg, b_wg);

    // qkv projection + feature map
    tf32_gemm<0><<<dim3(3 * Ss / 128, ROWS / 128, 1), 128>>>(w_in, b_in, nullptr, nullptr);

    ksum_kernel<<<Bb * Hh * HDk * 8 / 256, 256>>>();

    // state = normalized k^T v, per (b,h)
    tf32_gemm<2><<<dim3(HDk / 128, HDk / 128, Bb * Hh), 128>>>(nullptr, nullptr, nullptr, nullptr);

    memup_kernel<<<Hh * HDk * HDk / 256, 256>>>(mem);

    // y = read * (q @ mem_new), per (b,h)
    tf32_gemm<3><<<dim3(HDk / 128, NT / 128, Bb * Hh), 128>>>(nullptr, nullptr, nullptr, nullptr);

    // output projection + gated residual
    tf32_gemm<1><<<dim3(Dm / 128, ROWS / 128, 1), 128>>>(w_out, b_out, x, out);
}

// round 3
// speedup vs baseline: 3.5279x; 1.4321x over previous
#include <cuda_runtime.h>
#include <math.h>
#include <stdint.h>

// ---------------- problem constants ----------------
#define Bb   8
#define NT   1024
#define Dm   768
#define Hh   8
#define Ss   3072
#define HDk  384
#define ROWS (Bb * NT)            // 8192
#define EPSF 1e-6f
#define LNEPS 1e-5f
#define PERSISTF 0.95f

// ---------------- scratch (static device memory; no runtime alloc) ----------------
__device__ float g_xn[(size_t)ROWS * Dm];
__device__ float g_res[ROWS];
__device__ float g_xmean[Bb * Dm];
__device__ float g_read[Bb * Hh];
__device__ float g_write[Bb * Hh];
__device__ float g_qf[(size_t)Bb * Hh * NT * HDk];
__device__ float g_kf[(size_t)Bb * Hh * NT * HDk];
__device__ float g_v [(size_t)Bb * Hh * NT * HDk];
__device__ float g_ksum[Bb * Hh * HDk];
__device__ float g_state[(size_t)Bb * Hh * HDk * HDk];
__device__ float g_mem[Hh * HDk * HDk];
__device__ float g_y[(size_t)ROWS * Ss];

// ---------------- helpers ----------------
__device__ __forceinline__ float block_reduce_256(float v, float* sh) {
    __syncthreads();
    int lane = threadIdx.x & 31, w = threadIdx.x >> 5;
#pragma unroll
    for (int o = 16; o; o >>= 1) v += __shfl_down_sync(0xffffffffu, v, o);
    if (lane == 0) sh[w] = v;
    __syncthreads();
    if (threadIdx.x < 32) {
        v = (threadIdx.x < 8) ? sh[threadIdx.x] : 0.f;
#pragma unroll
        for (int o = 4; o; o >>= 1) v += __shfl_down_sync(0xffffffffu, v, o);
        if (threadIdx.x == 0) sh[0] = v;
    }
    __syncthreads();
    return sh[0];
}

__device__ __forceinline__ float sigmoidf_(float z) {
    return 1.f / (1.f + expf(-z));
}

__device__ __forceinline__ void mma_tf32(float4& d, const uint32_t a[4],
                                         const uint32_t b[2], const float4& c) {
    asm volatile(
        "mma.sync.aligned.m16n8k8.row.col.f32.tf32.tf32.f32 "
        "{%0,%1,%2,%3}, {%4,%5,%6,%7}, {%8,%9}, {%10,%11,%12,%13};\n"
        : "=f"(d.x), "=f"(d.y), "=f"(d.z), "=f"(d.w)
        : "r"(a[0]), "r"(a[1]), "r"(a[2]), "r"(a[3]),
          "r"(b[0]), "r"(b[1]),
          "f"(c.x), "f"(c.y), "f"(c.z), "f"(c.w));
}

__device__ __forceinline__ void cp16(float* smem_dst, const float* gsrc) {
    uint32_t sa = (uint32_t)__cvta_generic_to_shared(smem_dst);
    asm volatile("cp.async.cg.shared.global [%0], [%1], 16;\n" :: "r"(sa), "l"(gsrc));
}

// ---------------- 1) LayerNorm + residue gate ----------------
__global__ void ln_kernel(const float* __restrict__ x,
                          const float* __restrict__ lng,
                          const float* __restrict__ lnb,
                          const float* __restrict__ wres,
                          const float* __restrict__ bres) {
    __shared__ float sh[32];
    int row = blockIdx.x;
    const float* xr = x + (size_t)row * Dm;
    float v[3];
#pragma unroll
    for (int j = 0; j < 3; j++) v[j] = xr[threadIdx.x + 256 * j];
    float s  = v[0] + v[1] + v[2];
    float sq = v[0]*v[0] + v[1]*v[1] + v[2]*v[2];
    float tot  = block_reduce_256(s, sh);
    float totq = block_reduce_256(sq, sh);
    float mu   = tot * (1.f / Dm);
    float var  = totq * (1.f / Dm) - mu * mu;
    float rstd = rsqrtf(var + LNEPS);
    float dot = 0.f;
#pragma unroll
    for (int j = 0; j < 3; j++) {
        int i = threadIdx.x + 256 * j;
        float xn = (v[j] - mu) * rstd * lng[i] + lnb[i];
        g_xn[(size_t)row * Dm + i] = xn;
        dot += xn * wres[i];
    }
    float dt = block_reduce_256(dot, sh);
    if (threadIdx.x == 0) g_res[row] = sigmoidf_(dt + bres[0]);
}

// ---------------- 2) zero accumulators ----------------
__global__ void zero_kernel() {
    int i = blockIdx.x * 256 + threadIdx.x;
    if (i < Bb * Dm)        g_xmean[i] = 0.f;
    if (i < Bb * Hh * HDk)  g_ksum[i]  = 0.f;
}

// ---------------- 3) column mean of xn ----------------
__global__ void colmean_kernel() {
    int idx = blockIdx.x * 256 + threadIdx.x;         // < Bb*Dm*16
    int c   = idx / (Bb * Dm);
    int rem = idx % (Bb * Dm);
    int b = rem / Dm, d = rem % Dm;
    const float* p = g_xn + ((size_t)b * NT + (size_t)c * 64) * Dm + d;
    float s = 0.f;
#pragma unroll 4
    for (int n = 0; n < 64; n++) s += p[(size_t)n * Dm];
    atomicAdd(&g_xmean[rem], s);
}

// ---------------- 4) read/write gates ----------------
__global__ void gates_kernel(const float* __restrict__ wrg, const float* __restrict__ brg,
                             const float* __restrict__ wwg, const float* __restrict__ bwg) {
    int b = blockIdx.x, t = threadIdx.x;
    float ar[Hh], aw[Hh];
#pragma unroll
    for (int h = 0; h < Hh; h++) { ar[h] = 0.f; aw[h] = 0.f; }
    for (int d = t; d < Dm; d += 256) {
        float xm = g_xmean[b * Dm + d] * (1.f / NT);
        const float* wr = &wrg[d * Hh];
        const float* ww = &wwg[d * Hh];
#pragma unroll
        for (int h = 0; h < Hh; h++) {
            ar[h] = fmaf(xm, wr[h], ar[h]);
            aw[h] = fmaf(xm, ww[h], aw[h]);
        }
    }
    __shared__ float sr[Hh], sw[Hh];
    if (t < Hh) { sr[t] = 0.f; sw[t] = 0.f; }
    __syncthreads();
#pragma unroll
    for (int h = 0; h < Hh; h++) {
        float v = ar[h], w = aw[h];
#pragma unroll
        for (int o = 16; o; o >>= 1) {
            v += __shfl_down_sync(0xffffffffu, v, o);
            w += __shfl_down_sync(0xffffffffu, w, o);
        }
        if ((t & 31) == 0) { atomicAdd(&sr[h], v); atomicAdd(&sw[h], w); }
    }
    __syncthreads();
    if (t < Hh) {
        g_read[b * Hh + t]  = sigmoidf_(sr[t] + brg[t]);
        g_write[b * Hh + t] = sigmoidf_(sw[t] + bwg[t]);
    }
}

// ======================= TF32 tensor-core GEMM, cp.async double-buffered =======================
// 128x128x16 block tile, 256 threads (8 warps, 4x2 warp grid, 32x64 per warp).
// MODE 0: g_xn[8192,768] @ w_in[768,9216] (+b_in) -> hub feature map -> g_qf/g_kf/g_v
// MODE 1: g_y [8192,3072] @ w_out[3072,768] (+b_out) -> gated residual -> out
// MODE 2: per bh: kf^T[384,1024] @ v[1024,384] -> /(ksum+eps) -> g_state
// MODE 3: per bh: qf[1024,384] @ mem_new[384,384] -> *read -> g_y
#define AS_MK_STRIDE 20     // [128][16+4]
#define AS_KM_STRIDE 136    // [16][128+8]
#define BS_STRIDE    136    // [16][128+8]
#define AS_BUF_SZ    2560   // max(128*20, 16*136)
#define BS_BUF_SZ    2176

template <int MODE>
__global__ __launch_bounds__(256) void tf32_gemm(const float* __restrict__ Bsrc,
                                                 const float* __restrict__ bias,
                                                 const float* __restrict__ xin,
                                                 float* __restrict__ out) {
    constexpr int Kdim = (MODE == 0) ? Dm : (MODE == 1) ? Ss : (MODE == 2) ? NT : HDk;
    constexpr int ldb  = (MODE == 0) ? 3 * Ss : (MODE == 1) ? Dm : HDk;
    constexpr int NSTEP = Kdim / 16;

    const int bh = blockIdx.z;
    const float* A;
    const float* Bg;
    if (MODE == 0)      { A = g_xn;                         Bg = Bsrc; }
    else if (MODE == 1) { A = g_y;                          Bg = Bsrc; }
    else if (MODE == 2) { A = g_kf + (size_t)bh * NT * HDk; Bg = g_v + (size_t)bh * NT * HDk; }
    else                { A = g_qf + (size_t)bh * NT * HDk; Bg = g_mem + (size_t)(bh & 7) * HDk * HDk; }

    __shared__ float As[2][AS_BUF_SZ];
    __shared__ float Bsm[2][BS_BUF_SZ];

    const int t    = threadIdx.x;
    const int warp = t >> 5;
    const int lane = t & 31;
    const int lr   = lane >> 2;      // groupID 0..7
    const int lq   = lane & 3;       // tid-in-group 0..3
    const int wm   = (warp >> 1) * 32;
    const int wn   = (warp & 1) * 64;
    const int trow = blockIdx.y * 128;
    const int tcol = blockIdx.x * 128;

    // cp.async indices
    const int arow = t >> 2,  akq = (t & 3) * 4;   // A mk layout: rows t>>2 and +64
    const int bk   = t >> 5,  bn4 = (t & 31) * 4;  // B / A-km layout: k rows t>>5 and +8

    auto issue = [&](int k0, int buf) {
        if (MODE == 2) {
            cp16(&As[buf][bk * AS_KM_STRIDE + bn4],
                 A + (size_t)(k0 + bk) * HDk + trow + bn4);
            cp16(&As[buf][(bk + 8) * AS_KM_STRIDE + bn4],
                 A + (size_t)(k0 + bk + 8) * HDk + trow + bn4);
        } else {
            cp16(&As[buf][arow * AS_MK_STRIDE + akq],
                 A + (size_t)(trow + arow) * Kdim + k0 + akq);
            cp16(&As[buf][(arow + 64) * AS_MK_STRIDE + akq],
                 A + (size_t)(trow + arow + 64) * Kdim + k0 + akq);
        }
        cp16(&Bsm[buf][bk * BS_STRIDE + bn4],
             Bg + (size_t)(k0 + bk) * ldb + tcol + bn4);
        cp16(&Bsm[buf][(bk + 8) * BS_STRIDE + bn4],
             Bg + (size_t)(k0 + bk + 8) * ldb + tcol + bn4);
        asm volatile("cp.async.commit_group;\n" ::);
    };

    float4 acc[2][8];
#pragma unroll
    for (int i = 0; i < 2; i++)
#pragma unroll
        for (int j = 0; j < 8; j++) acc[i][j] = make_float4(0.f, 0.f, 0.f, 0.f);

    issue(0, 0);

    for (int s = 0; s < NSTEP; s++) {
        if (s + 1 < NSTEP) {
            issue((s + 1) * 16, (s + 1) & 1);
            asm volatile("cp.async.wait_group 1;\n" ::);
        } else {
            asm volatile("cp.async.wait_group 0;\n" ::);
        }
        __syncthreads();

        const float* as = As[s & 1];
        const float* bs = Bsm[s & 1];

#pragma unroll
        for (int kb = 0; kb < 2; kb++) {
            const int ko = kb * 8;
            uint32_t afr[2][4], bfr[8][2];
#pragma unroll
            for (int mt = 0; mt < 2; mt++) {
                int mb = wm + mt * 16 + lr;
                if (MODE == 2) {
                    afr[mt][0] = __float_as_uint(as[(ko + lq)     * AS_KM_STRIDE + mb]);
                    afr[mt][1] = __float_as_uint(as[(ko + lq)     * AS_KM_STRIDE + mb + 8]);
                    afr[mt][2] = __float_as_uint(as[(ko + lq + 4) * AS_KM_STRIDE + mb]);
                    afr[mt][3] = __float_as_uint(as[(ko + lq + 4) * AS_KM_STRIDE + mb + 8]);
                } else {
                    afr[mt][0] = __float_as_uint(as[mb       * AS_MK_STRIDE + ko + lq]);
                    afr[mt][1] = __float_as_uint(as[(mb + 8) * AS_MK_STRIDE + ko + lq]);
                    afr[mt][2] = __float_as_uint(as[mb       * AS_MK_STRIDE + ko + lq + 4]);
                    afr[mt][3] = __float_as_uint(as[(mb + 8) * AS_MK_STRIDE + ko + lq + 4]);
                }
            }
#pragma unroll
            for (int nt = 0; nt < 8; nt++) {
                int nb = wn + nt * 8 + lr;
                bfr[nt][0] = __float_as_uint(bs[(ko + lq)     * BS_STRIDE + nb]);
                bfr[nt][1] = __float_as_uint(bs[(ko + lq + 4) * BS_STRIDE + nb]);
            }
#pragma unroll
            for (int mt = 0; mt < 2; mt++)
#pragma unroll
                for (int nt = 0; nt < 8; nt++)
                    mma_tf32(acc[mt][nt], afr[mt], bfr[nt], acc[mt][nt]);
        }
        __syncthreads();
    }

    // -------- epilogue (float2 stores; c0 is always even) --------
    auto epi2 = [&](int row, int col, float v0, float v1) {
        if (MODE == 0) {
            float a = v0 + bias[col], b2 = v1 + bias[col + 1];
            int b = row >> 10, n = row & 1023;
            int region = col / Ss;
            int sIn = col - region * Ss;
            int h = sIn / HDk, d = sIn - h * HDk;
            size_t idx = (((size_t)(b * Hh + h)) * NT + n) * HDk + d;
            if (region == 2) {
                *(float2*)&g_v[idx] = make_float2(a, b2);
            } else {
                float p0 = fmaxf(a, 0.f) + EPSF;
                float p1 = fmaxf(b2, 0.f) + EPSF;
                float f0 = p0 * sqrtf(p0);
                float f1 = p1 * sqrtf(p1);
                float* dst = (region == 0) ? g_qf : g_kf;
                *(float2*)&dst[idx] = make_float2(f0, f1);
            }
        } else if (MODE == 1) {
            float a = v0 + bias[col], b2 = v1 + bias[col + 1];
            float r = g_res[row];
            size_t o = (size_t)row * Dm + col;
            float2 xi = *(const float2*)&xin[o];
            *(float2*)&out[o] = make_float2(r * a + (1.f - r) * xi.x,
                                            r * b2 + (1.f - r) * xi.y);
        } else if (MODE == 2) {
            float inv = 1.f / (g_ksum[bh * HDk + row] + EPSF);
            size_t o = ((size_t)bh * HDk + row) * HDk + col;
            *(float2*)&g_state[o] = make_float2(v0 * inv, v1 * inv);
        } else {
            float rg = g_read[bh];
            int b = bh >> 3, h = bh & 7;
            size_t o = ((size_t)(b * NT + row)) * Ss + h * HDk + col;
            *(float2*)&g_y[o] = make_float2(rg * v0, rg * v1);
        }
    };

#pragma unroll
    for (int mt = 0; mt < 2; mt++) {
#pragma unroll
        for (int nt = 0; nt < 8; nt++) {
            float4 c = acc[mt][nt];
            int r0 = trow + wm + mt * 16 + lr;
            int c0 = tcol + wn + nt * 8 + 2 * lq;
            epi2(r0,     c0, c.x, c.y);
            epi2(r0 + 8, c0, c.z, c.w);
        }
    }
}

// ---------------- ksum over tokens ----------------
__global__ void ksum_kernel() {
    int idx = blockIdx.x * 256 + threadIdx.x;           // < Bb*Hh*HDk*8
    int c   = idx / (Bb * Hh * HDk);
    int rem = idx % (Bb * Hh * HDk);
    int bh = rem / HDk, d = rem % HDk;
    const float* p = g_kf + ((size_t)bh * NT + (size_t)c * 128) * HDk + d;
    float s = 0.f;
#pragma unroll 4
    for (int n = 0; n < 128; n++) s += p[(size_t)n * HDk];
    atomicAdd(&g_ksum[rem], s);
}

// ---------------- EMA memory update ----------------
__global__ void memup_kernel(const float* __restrict__ mem) {
    int idx = blockIdx.x * 256 + threadIdx.x;           // < Hh*HDk*HDk
    int h  = idx / (HDk * HDk);
    int de = idx - h * HDk * HDk;
    float ss = 0.f, sw = 0.f;
#pragma unroll
    for (int b = 0; b < Bb; b++) {
        ss += g_state[((size_t)(b * Hh + h)) * HDk * HDk + de];
        sw += g_write[b * Hh + h];
    }
    g_mem[idx] = PERSISTF * mem[idx]
               + (1.f - PERSISTF) * (sw * (1.f / Bb)) * (ss * (1.f / Bb));
}

// ---------------- launch ----------------
extern "C" void kernel_launch(void* const* d_in, const int* in_sizes, int n_in,
                              void* d_out, int out_size) {
    const float* x     = (const float*)d_in[0];
    const float* mem   = (const float*)d_in[1];
    const float* lng   = (const float*)d_in[2];
    const float* lnb   = (const float*)d_in[3];
    const float* w_in  = (const float*)d_in[4];
    const float* b_in  = (const float*)d_in[5];
    const float* w_out = (const float*)d_in[6];
    const float* b_out = (const float*)d_in[7];
    const float* w_rg  = (const float*)d_in[8];
    const float* b_rg  = (const float*)d_in[9];
    const float* w_wg  = (const float*)d_in[10];
    const float* b_wg  = (const float*)d_in[11];
    const float* w_res = (const float*)d_in[12];
    const float* b_res = (const float*)d_in[13];
    float* out = (float*)d_out;

    ln_kernel<<<ROWS, 256>>>(x, lng, lnb, w_res, b_res);
    zero_kernel<<<(Bb * Hh * HDk + 255) / 256, 256>>>();
    colmean_kernel<<<Bb * Dm * 16 / 256, 256>>>();
    gates_kernel<<<Bb, 256>>>(w_rg, b_rg, w_wg, b_wg);

    tf32_gemm<0><<<dim3(3 * Ss / 128, ROWS / 128, 1), 256>>>(w_in, b_in, nullptr, nullptr);

    ksum_kernel<<<Bb * Hh * HDk * 8 / 256, 256>>>();

    tf32_gemm<2><<<dim3(HDk / 128, HDk / 128, Bb * Hh), 256>>>(nullptr, nullptr, nullptr, nullptr);

    memup_kernel<<<Hh * HDk * HDk / 256, 256>>>(mem);

    tf32_gemm<3><<<dim3(HDk / 128, NT / 128, Bb * Hh), 256>>>(nullptr, nullptr, nullptr, nullptr);

    tf32_gemm<1><<<dim3(Dm / 128, ROWS / 128, 1), 256>>>(w_out, b_out, x, out);
}